// round 4
// baseline (speedup 1.0000x reference)
#include <cuda_runtime.h>
#include <cstdint>

#define Bsz 8
#define Nn 5000
#define NPB 6
#define NWARP 6
#define THREADS 192
#define SRD 68                 // padded row stride (floats) for all smem tiles

typedef unsigned long long u64;

// ---------------- helpers ----------------
__device__ __forceinline__ uint32_t f2tf(float f) {
    uint32_t r; asm("cvt.rna.tf32.f32 %0, %1;" : "=r"(r) : "f"(f)); return r;
}
__device__ __forceinline__ u64 fma2(u64 a, u64 b, u64 c) {
    u64 d; asm("fma.rn.f32x2 %0, %1, %2, %3;" : "=l"(d) : "l"(a), "l"(b), "l"(c)); return d;
}
__device__ __forceinline__ u64 mul2(u64 a, u64 b) {
    u64 d; asm("mul.rn.f32x2 %0, %1, %2;" : "=l"(d) : "l"(a), "l"(b)); return d;
}
__device__ __forceinline__ u64 dup2(float x) {
    u64 d; unsigned r = __float_as_uint(x);
    asm("mov.b64 %0, {%1, %1};" : "=l"(d) : "r"(r)); return d;
}
__device__ __forceinline__ float2 unpack2(u64 v) {
    unsigned lo, hi;
    asm("mov.b64 {%0, %1}, %2;" : "=r"(lo), "=r"(hi) : "l"(v));
    return make_float2(__uint_as_float(lo), __uint_as_float(hi));
}
__device__ __forceinline__ void mma_tf32(float d[4], const uint32_t a[4],
                                         uint32_t b0, uint32_t b1) {
    asm volatile(
        "mma.sync.aligned.m16n8k8.row.col.f32.tf32.tf32.f32 "
        "{%0,%1,%2,%3}, {%4,%5,%6,%7}, {%8,%9}, {%0,%1,%2,%3};"
        : "+f"(d[0]), "+f"(d[1]), "+f"(d[2]), "+f"(d[3])
        : "r"(a[0]), "r"(a[1]), "r"(a[2]), "r"(a[3]), "r"(b0), "r"(b1));
}

// ---------------- staging ----------------
// Weight -> smem [n][k], stride 68, tf32-converted. All 192 threads.
__device__ __forceinline__ void stage_weight(const float* __restrict__ Wg,
                                             uint32_t* __restrict__ sW, int tid)
{
#pragma unroll
    for (int i = 0; i < 6; i++) {
        int idx = tid + i * THREADS;          // 0..1151, need 1024
        if (idx < 1024) {
            const int n = idx >> 4, c4 = idx & 15;
            const float4 v = *(const float4*)(Wg + n * 64 + c4 * 4);
            uint4 u = make_uint4(f2tf(v.x), f2tf(v.y), f2tf(v.z), f2tf(v.w));
            *(uint4*)(sW + n * SRD + c4 * 4) = u;
        }
    }
}

// Input slab for one node -> warp's A buffer rows 0..11 (tf32).
__device__ __forceinline__ void stage_input(const float* __restrict__ src,
                                            uint32_t* __restrict__ sA,
                                            int b, int n, int lane)
{
#pragma unroll
    for (int i = 0; i < 6; i++) {
        const int idx = lane + i * 32;        // 0..191
        const int t = idx >> 4, c4 = idx & 15;
        const float4 v = *(const float4*)(src + ((size_t)(b * 12 + t) * Nn + n) * 64 + c4 * 4);
        uint4 u = make_uint4(f2tf(v.x), f2tf(v.y), f2tf(v.z), f2tf(v.w));
        *(uint4*)(sA + t * SRD + c4 * 4) = u;
    }
}

// ---------------- warp GEMM: [16(12),64] x [64,64]^T -> d[8][4] ----------------
__device__ __forceinline__ void gemm_warp(const uint32_t* __restrict__ sA,
                                          const uint32_t* __restrict__ sW,
                                          float d[8][4], int lane)
{
    const int gid = lane >> 2, tig = lane & 3;
    uint32_t a[8][4];
#pragma unroll
    for (int ks = 0; ks < 8; ks++) {
        const uint32_t* r0 = sA + gid * SRD + ks * 8 + tig;
        const uint32_t* r1 = sA + (gid + 8) * SRD + ks * 8 + tig;
        a[ks][0] = r0[0]; a[ks][1] = r1[0];
        a[ks][2] = r0[4]; a[ks][3] = r1[4];
    }
#pragma unroll
    for (int nt = 0; nt < 8; nt++) {
        d[nt][0] = 0.f; d[nt][1] = 0.f; d[nt][2] = 0.f; d[nt][3] = 0.f;
        const uint32_t* wrow = sW + (nt * 8 + gid) * SRD + tig;
#pragma unroll
        for (int ks = 0; ks < 8; ks++) {
            const uint32_t b0 = wrow[ks * 8];
            const uint32_t b1 = wrow[ks * 8 + 4];
            mma_tf32(d[nt], a[ks], b0, b1);
        }
    }
}

// epilogue -> f32 smem buffer (bias + relu), rows 0..11 only
__device__ __forceinline__ void epi_f32(const float d[8][4], float* __restrict__ dst,
                                        const float* __restrict__ bi, int lane)
{
    const int gid = lane >> 2, tig = lane & 3;
#pragma unroll
    for (int nt = 0; nt < 8; nt++) {
        const int c = nt * 8 + tig * 2;
        float2 v0 = make_float2(fmaxf(d[nt][0] + bi[c], 0.f),
                                fmaxf(d[nt][1] + bi[c + 1], 0.f));
        *(float2*)(dst + gid * SRD + c) = v0;
        if (gid < 4) {
            float2 v1 = make_float2(fmaxf(d[nt][2] + bi[c], 0.f),
                                    fmaxf(d[nt][3] + bi[c + 1], 0.f));
            *(float2*)(dst + (gid + 8) * SRD + c) = v1;
        }
    }
}

// epilogue -> tf32 smem A buffer (bias + relu)
__device__ __forceinline__ void epi_tf32(const float d[8][4], uint32_t* __restrict__ dst,
                                         const float* __restrict__ bi, int lane)
{
    const int gid = lane >> 2, tig = lane & 3;
#pragma unroll
    for (int nt = 0; nt < 8; nt++) {
        const int c = nt * 8 + tig * 2;
        uint2 v0 = make_uint2(f2tf(fmaxf(d[nt][0] + bi[c], 0.f)),
                              f2tf(fmaxf(d[nt][1] + bi[c + 1], 0.f)));
        *(uint2*)(dst + gid * SRD + c) = v0;
        if (gid < 4) {
            uint2 v1 = make_uint2(f2tf(fmaxf(d[nt][2] + bi[c], 0.f)),
                                  f2tf(fmaxf(d[nt][3] + bi[c + 1], 0.f)));
            *(uint2*)(dst + (gid + 8) * SRD + c) = v1;
        }
    }
}

// ---------------- attention: one node per warp ----------------
// lane = qgroup*8 + head ; qgroup handles 3 q's, head owns 8 dims.
__device__ __forceinline__ void attention(const float* __restrict__ sQ,
                                          const float* __restrict__ sK,
                                          const float* __restrict__ sV,
                                          uint32_t* __restrict__ sA, int lane)
{
    const int h8 = (lane & 7) * 8;
    const int qbase = (lane >> 3) * 3;
    const float scale = 0.35355339059327373f;   // 1/sqrt(8)
#pragma unroll
    for (int j = 0; j < 3; j++) {
        const int q = qbase + j;
        u64 qp[4];
#pragma unroll
        for (int e = 0; e < 4; e++)
            qp[e] = *(const u64*)(sQ + q * SRD + h8 + 2 * e);

        float s[12];
        float mx = -1e30f;
#pragma unroll
        for (int p = 0; p < 12; p++) {
            const float* kr = sK + p * SRD + h8;
            u64 dd = fma2(qp[0], *(const u64*)(kr + 0),
                     fma2(qp[1], *(const u64*)(kr + 2),
                     fma2(qp[2], *(const u64*)(kr + 4),
                     mul2(qp[3], *(const u64*)(kr + 6)))));
            float2 t = unpack2(dd);
            s[p] = (t.x + t.y) * scale;
            mx = fmaxf(mx, s[p]);
        }
        float sum = 0.f;
#pragma unroll
        for (int p = 0; p < 12; p++) { s[p] = __expf(s[p] - mx); sum += s[p]; }
        const float inv = __fdividef(1.f, sum);

        u64 o[4];
        const u64 z = dup2(0.f);
#pragma unroll
        for (int e = 0; e < 4; e++) o[e] = z;
#pragma unroll
        for (int p = 0; p < 12; p++) {
            const u64 a = dup2(s[p] * inv);
            const float* vr = sV + p * SRD + h8;
#pragma unroll
            for (int e = 0; e < 4; e++)
                o[e] = fma2(*(const u64*)(vr + 2 * e), a, o[e]);
        }
        float2 e0 = unpack2(o[0]), e1 = unpack2(o[1]);
        float2 e2 = unpack2(o[2]), e3 = unpack2(o[3]);
        uint4 u0 = make_uint4(f2tf(e0.x), f2tf(e0.y), f2tf(e1.x), f2tf(e1.y));
        uint4 u1 = make_uint4(f2tf(e2.x), f2tf(e2.y), f2tf(e3.x), f2tf(e3.y));
        *(uint4*)(sA + q * SRD + h8)     = u0;
        *(uint4*)(sA + q * SRD + h8 + 4) = u1;
    }
}

// ---------------- kernel ----------------
__global__ void __launch_bounds__(THREADS)
fused_mma_kernel(const float* __restrict__ X,
                 const float* __restrict__ STE_P,
                 const float* __restrict__ STE_Q,
                 const float* __restrict__ W21, const float* __restrict__ b21,
                 const float* __restrict__ W22, const float* __restrict__ b22,
                 const float* __restrict__ W23, const float* __restrict__ b23,
                 const float* __restrict__ W24, const float* __restrict__ b24,
                 const float* __restrict__ W25, const float* __restrict__ b25,
                 float* __restrict__ Out)
{
    extern __shared__ float smem[];
    uint32_t* sW    = (uint32_t*)smem;                 // 64*68
    float*    sBias = smem + 64 * SRD;                 // 5*64
    float*    base  = sBias + 5 * 64;
    // per warp: A(16*68 tf32) | Q | K | V (12*68 f32 each)
    const int WARP_FLTS = (16 + 3 * 12) * SRD;

    const int tid  = threadIdx.x;
    const int w    = tid >> 5;
    const int lane = tid & 31;
    const int b    = blockIdx.y;
    const int n    = blockIdx.x * NPB + w;
    const bool valid = (n < Nn);

    uint32_t* myA = (uint32_t*)(base + w * WARP_FLTS);
    float*    myQ = base + w * WARP_FLTS + 16 * SRD;
    float*    myK = myQ + 12 * SRD;
    float*    myV = myK + 12 * SRD;

    if (tid < 64) {
        sBias[tid]       = b21[tid];
        sBias[64 + tid]  = b22[tid];
        sBias[128 + tid] = b23[tid];
        sBias[192 + tid] = b24[tid];
        sBias[256 + tid] = b25[tid];
    }

    const float* srcs[3] = { STE_Q, STE_P, X };
    const float* wgts[3] = { W21, W22, W23 };
    float* qkv[3] = { myQ, myK, myV };

    float d[8][4];

    // -------- Phases A/B/C: projections --------
#pragma unroll 1
    for (int ph = 0; ph < 3; ph++) {
        stage_weight(wgts[ph], sW, tid);
        if (valid) stage_input(srcs[ph], myA, b, n, lane);
        __syncthreads();
        gemm_warp(myA, sW, d, lane);
        epi_f32(d, qkv[ph], sBias + ph * 64, lane);
        __syncthreads();
    }

    // -------- Attention (warp-local) + stage W24 --------
    if (valid) attention(myQ, myK, myV, myA, lane);
    stage_weight(W24, sW, tid);
    __syncthreads();

    // -------- Phase D: h = relu(attn @ W24^T + b24) -> myA (tf32) --------
    gemm_warp(myA, sW, d, lane);
    epi_tf32(d, myA, sBias + 192, lane);
    __syncthreads();

    stage_weight(W25, sW, tid);
    __syncthreads();

    // -------- Phase E: out = h @ W25^T + b25 -> global --------
    gemm_warp(myA, sW, d, lane);
    if (valid) {
        const int gid = lane >> 2, tig = lane & 3;
        const float* bi = sBias + 256;
        float* o0 = Out + ((size_t)(b * 12 + gid) * Nn + n) * 64;
        float* o1 = Out + ((size_t)(b * 12 + gid + 8) * Nn + n) * 64;
#pragma unroll
        for (int nt = 0; nt < 8; nt++) {
            const int c = nt * 8 + tig * 2;
            *(float2*)(o0 + c) = make_float2(d[nt][0] + bi[c], d[nt][1] + bi[c + 1]);
            if (gid < 4)
                *(float2*)(o1 + c) = make_float2(d[nt][2] + bi[c], d[nt][3] + bi[c + 1]);
        }
    }
}

extern "C" void kernel_launch(void* const* d_in, const int* in_sizes, int n_in,
                              void* d_out, int out_size)
{
    const float* X     = (const float*)d_in[0];
    const float* STE_P = (const float*)d_in[1];
    const float* STE_Q = (const float*)d_in[2];
    const float* W21   = (const float*)d_in[3];
    const float* b21   = (const float*)d_in[4];
    const float* W22   = (const float*)d_in[5];
    const float* b22   = (const float*)d_in[6];
    const float* W23   = (const float*)d_in[7];
    const float* b23   = (const float*)d_in[8];
    const float* W24   = (const float*)d_in[9];
    const float* b24   = (const float*)d_in[10];
    const float* W25   = (const float*)d_in[11];
    const float* b25   = (const float*)d_in[12];
    float* Out = (float*)d_out;

    const size_t smem_bytes =
        (size_t)(64 * SRD + 5 * 64 + NWARP * (16 + 3 * 12) * SRD) * sizeof(float); // 103,552

    cudaFuncSetAttribute(fused_mma_kernel,
                         cudaFuncAttributeMaxDynamicSharedMemorySize,
                         (int)smem_bytes);

    dim3 grid((Nn + NPB - 1) / NPB, Bsz);   // (834, 8)
    fused_mma_kernel<<<grid, THREADS, smem_bytes>>>(
        X, STE_P, STE_Q,
        W21, b21, W22, b22, W23, b23, W24, b24, W25, b25,
        Out);
}

// round 5
// speedup vs baseline: 1.6316x; 1.6316x over previous
#include <cuda_runtime.h>
#include <cstdint>

#define Bsz 8
#define Nn 5000
#define NODES 8            // nodes per block
#define THREADS 192        // 6 warps
#define ROWS 96            // 8 nodes * 12 timesteps, fully packed M
#define AST 66             // stride (floats) of A-slab / Q / K rows
#define WST 68             // weight tile stride (conflict-free B-frag reads)

typedef unsigned long long u64;

// ---------------- scalar helpers ----------------
__device__ __forceinline__ uint32_t f2tf(float f) {
    uint32_t r; asm("cvt.rna.tf32.f32 %0, %1;" : "=r"(r) : "f"(f)); return r;
}
__device__ __forceinline__ float f2tf_f(float f) { return __uint_as_float(f2tf(f)); }
__device__ __forceinline__ u64 fma2(u64 a, u64 b, u64 c) {
    u64 d; asm("fma.rn.f32x2 %0, %1, %2, %3;" : "=l"(d) : "l"(a), "l"(b), "l"(c)); return d;
}
__device__ __forceinline__ u64 mul2(u64 a, u64 b) {
    u64 d; asm("mul.rn.f32x2 %0, %1, %2;" : "=l"(d) : "l"(a), "l"(b)); return d;
}
__device__ __forceinline__ u64 dup2(float x) {
    u64 d; unsigned r = __float_as_uint(x);
    asm("mov.b64 %0, {%1, %1};" : "=l"(d) : "r"(r)); return d;
}
__device__ __forceinline__ float2 unpack2(u64 v) {
    unsigned lo, hi;
    asm("mov.b64 {%0, %1}, %2;" : "=r"(lo), "=r"(hi) : "l"(v));
    return make_float2(__uint_as_float(lo), __uint_as_float(hi));
}
__device__ __forceinline__ void mma_tf32(float d[4], const uint32_t a[4],
                                         uint32_t b0, uint32_t b1) {
    asm volatile(
        "mma.sync.aligned.m16n8k8.row.col.f32.tf32.tf32.f32 "
        "{%0,%1,%2,%3}, {%4,%5,%6,%7}, {%8,%9}, {%0,%1,%2,%3};"
        : "+f"(d[0]), "+f"(d[1]), "+f"(d[2]), "+f"(d[3])
        : "r"(a[0]), "r"(a[1]), "r"(a[2]), "r"(a[3]), "r"(b0), "r"(b1));
}

// global row pointer for packed row rp (node = rp/12, t = rp%12)
__device__ __forceinline__ const float* grow(const float* __restrict__ src,
                                             int b, int n0, int rp) {
    const int n = rp / 12;
    const int t = rp - n * 12;
    return src + ((size_t)(b * 12 + t) * Nn + (n0 + n)) * 64;
}

// ---------------- staging ----------------
__device__ __forceinline__ void stage_weight(const float* __restrict__ Wg,
                                             float* __restrict__ sW, int tid)
{
#pragma unroll
    for (int i = 0; i < 6; i++) {
        const int idx = tid + i * THREADS;
        if (idx < 1024) {
            const int nn = idx >> 4, c4 = idx & 15;
            const float4 v = *(const float4*)(Wg + nn * 64 + c4 * 4);
            float4 u = make_float4(f2tf_f(v.x), f2tf_f(v.y), f2tf_f(v.z), f2tf_f(v.w));
            *(float4*)(sW + nn * WST + c4 * 4) = u;
        }
    }
}

// ---------------- warp fragments / mma ----------------
__device__ __forceinline__ void load_frags(uint32_t a[8][4], const float* __restrict__ sA,
                                           int row0, int gid, int tig)
{
    const float* r0 = sA + (row0 + gid) * AST + tig;
    const float* r1 = r0 + 8 * AST;
#pragma unroll
    for (int ks = 0; ks < 8; ks++) {
        a[ks][0] = __float_as_uint(r0[ks * 8]);
        a[ks][1] = __float_as_uint(r1[ks * 8]);
        a[ks][2] = __float_as_uint(r0[ks * 8 + 4]);
        a[ks][3] = __float_as_uint(r1[ks * 8 + 4]);
    }
}

__device__ __forceinline__ void mma_all(float d[8][4], const uint32_t a[8][4],
                                        const float* __restrict__ sW, int gid, int tig)
{
#pragma unroll
    for (int nt = 0; nt < 8; nt++) {
        d[nt][0] = 0.f; d[nt][1] = 0.f; d[nt][2] = 0.f; d[nt][3] = 0.f;
        const float* wrow = sW + (nt * 8 + gid) * WST + tig;
#pragma unroll
        for (int ks = 0; ks < 8; ks++) {
            const uint32_t b0 = __float_as_uint(wrow[ks * 8]);
            const uint32_t b1 = __float_as_uint(wrow[ks * 8 + 4]);
            mma_tf32(d[nt], a[ks], b0, b1);
        }
    }
}

// ---------------- epilogues ----------------
__device__ __forceinline__ void epi_smem(const float d[8][4], float* __restrict__ dst,
                                         const float* __restrict__ bi,
                                         int row0, int gid, int tig)
{
    float* p0 = dst + (row0 + gid) * AST;
    float* p1 = p0 + 8 * AST;
#pragma unroll
    for (int nt = 0; nt < 8; nt++) {
        const int c = nt * 8 + tig * 2;
        *(float2*)(p0 + c) = make_float2(fmaxf(d[nt][0] + bi[c], 0.f),
                                         fmaxf(d[nt][1] + bi[c + 1], 0.f));
        *(float2*)(p1 + c) = make_float2(fmaxf(d[nt][2] + bi[c], 0.f),
                                         fmaxf(d[nt][3] + bi[c + 1], 0.f));
    }
}

__device__ __forceinline__ void epi_tf32(const float d[8][4], float* __restrict__ dst,
                                         const float* __restrict__ bi,
                                         int row0, int gid, int tig)
{
    float* p0 = dst + (row0 + gid) * AST;
    float* p1 = p0 + 8 * AST;
#pragma unroll
    for (int nt = 0; nt < 8; nt++) {
        const int c = nt * 8 + tig * 2;
        *(float2*)(p0 + c) = make_float2(f2tf_f(fmaxf(d[nt][0] + bi[c], 0.f)),
                                         f2tf_f(fmaxf(d[nt][1] + bi[c + 1], 0.f)));
        *(float2*)(p1 + c) = make_float2(f2tf_f(fmaxf(d[nt][2] + bi[c], 0.f)),
                                         f2tf_f(fmaxf(d[nt][3] + bi[c + 1], 0.f)));
    }
}

// ---------------- kernel ----------------
__global__ void __launch_bounds__(THREADS, 2)
fused_mma_kernel(const float* __restrict__ X,
                 const float* __restrict__ STE_P,
                 const float* __restrict__ STE_Q,
                 const float* __restrict__ W21, const float* __restrict__ b21,
                 const float* __restrict__ W22, const float* __restrict__ b22,
                 const float* __restrict__ W23, const float* __restrict__ b23,
                 const float* __restrict__ W24, const float* __restrict__ b24,
                 const float* __restrict__ W25, const float* __restrict__ b25,
                 float* __restrict__ Out)
{
    extern __shared__ float sm[];
    float* sW0   = sm;                      // 64*68
    float* sW1   = sm + 64 * WST;           // 64*68
    float* sBias = sm + 2 * 64 * WST;       // 5*64
    float* sA    = sBias + 320;             // 96*66 (input / V / attn / hidden)
    float* sQ    = sA + ROWS * AST;         // 96*66
    float* sK    = sQ + ROWS * AST;         // 96*66

    const int tid  = threadIdx.x;
    const int w    = tid >> 5;
    const int lane = tid & 31;
    const int gid  = lane >> 2;
    const int tig  = lane & 3;
    const int b    = blockIdx.y;
    const int n0   = blockIdx.x * NODES;
    const int row0 = w * 16;

    if (tid < 64) {
        sBias[tid]       = b21[tid];
        sBias[64 + tid]  = b22[tid];
        sBias[128 + tid] = b23[tid];
        sBias[192 + tid] = b24[tid];
        sBias[256 + tid] = b25[tid];
    }

    // stage W21 + this warp's 16 rows of STE_Q (tf32)
    stage_weight(W21, sW0, tid);
#pragma unroll
    for (int i = 0; i < 16; i++) {
        const float2 v = *(const float2*)(grow(STE_Q, b, n0, row0 + i) + 2 * lane);
        *(float2*)(sA + (row0 + i) * AST + 2 * lane) =
            make_float2(f2tf_f(v.x), f2tf_f(v.y));
    }
    __syncthreads();                                             // 1: W21 + inputs ready

    uint32_t a[8][4];
    float d[8][4];
    float2 pf[16];

    // ---------------- phase A: q = relu(STE_Q @ W21^T + b21) -> sQ ----------------
#pragma unroll
    for (int i = 0; i < 16; i++)
        pf[i] = *(const float2*)(grow(STE_P, b, n0, row0 + i) + 2 * lane);
    load_frags(a, sA, row0, gid, tig);
    __syncwarp();
#pragma unroll
    for (int i = 0; i < 16; i++)
        *(float2*)(sA + (row0 + i) * AST + 2 * lane) =
            make_float2(f2tf_f(pf[i].x), f2tf_f(pf[i].y));
    stage_weight(W22, sW1, tid);
    mma_all(d, a, sW0, gid, tig);
    epi_smem(d, sQ, sBias, row0, gid, tig);
    __syncthreads();                                             // 2: W22 ready, sW0 free

    // ---------------- phase B: k = relu(STE_P @ W22^T + b22) -> sK ----------------
#pragma unroll
    for (int i = 0; i < 16; i++)
        pf[i] = *(const float2*)(grow(X, b, n0, row0 + i) + 2 * lane);
    load_frags(a, sA, row0, gid, tig);
    __syncwarp();
#pragma unroll
    for (int i = 0; i < 16; i++)
        *(float2*)(sA + (row0 + i) * AST + 2 * lane) =
            make_float2(f2tf_f(pf[i].x), f2tf_f(pf[i].y));
    stage_weight(W23, sW0, tid);
    mma_all(d, a, sW1, gid, tig);
    epi_smem(d, sK, sBias + 64, row0, gid, tig);
    __syncthreads();                                             // 3: W23 ready, sW1 free

    // ---------------- phase C: v = relu(X @ W23^T + b23) -> sA (in place) ---------
    load_frags(a, sA, row0, gid, tig);
    __syncwarp();
    stage_weight(W24, sW1, tid);
    mma_all(d, a, sW0, gid, tig);
    epi_smem(d, sA, sBias + 128, row0, gid, tig);                // V over X, own rows
    __syncthreads();                                             // 4: Q,K,V complete

    // ---------------- attention: per (node, q, 4 heads) thread ----------------
    // tid -> nd = tid/24 ; q = (tid%24)%12 ; hp = (tid%24)/12 (head-half)
    u64 o[16];
    {
        const int nd  = tid / 24;
        const int sub = tid - nd * 24;
        const int q   = sub % 12;
        const int hp  = sub / 12;
        const float* Qr = sQ + (nd * 12 + q) * AST + hp * 32;
        const float* Kb = sK + nd * 12 * AST + hp * 32;
        const float* Vb = sA + nd * 12 * AST + hp * 32;
        const float scale = 0.35355339059327373f;               // 1/sqrt(8)
#pragma unroll
        for (int hh = 0; hh < 4; hh++) {
            const u64 q0 = *(const u64*)(Qr + 8 * hh + 0);
            const u64 q1 = *(const u64*)(Qr + 8 * hh + 2);
            const u64 q2 = *(const u64*)(Qr + 8 * hh + 4);
            const u64 q3 = *(const u64*)(Qr + 8 * hh + 6);
            float s[12];
            float mx = -1e30f;
#pragma unroll
            for (int p = 0; p < 12; p++) {
                const float* kr = Kb + p * AST + 8 * hh;
                u64 dd = fma2(q0, *(const u64*)(kr + 0),
                         fma2(q1, *(const u64*)(kr + 2),
                         fma2(q2, *(const u64*)(kr + 4),
                         mul2(q3, *(const u64*)(kr + 6)))));
                float2 t = unpack2(dd);
                s[p] = (t.x + t.y) * scale;
                mx = fmaxf(mx, s[p]);
            }
            float sum = 0.f;
#pragma unroll
            for (int p = 0; p < 12; p++) { s[p] = __expf(s[p] - mx); sum += s[p]; }
            const float inv = __fdividef(1.f, sum);
            const u64 z = dup2(0.f);
            u64 o0 = z, o1 = z, o2 = z, o3 = z;
#pragma unroll
            for (int p = 0; p < 12; p++) {
                const u64 aw = dup2(s[p] * inv);
                const float* vr = Vb + p * AST + 8 * hh;
                o0 = fma2(*(const u64*)(vr + 0), aw, o0);
                o1 = fma2(*(const u64*)(vr + 2), aw, o1);
                o2 = fma2(*(const u64*)(vr + 4), aw, o2);
                o3 = fma2(*(const u64*)(vr + 6), aw, o3);
            }
            o[4 * hh + 0] = o0; o[4 * hh + 1] = o1;
            o[4 * hh + 2] = o2; o[4 * hh + 3] = o3;
        }
    }
    stage_weight(W25, sW0, tid);
    __syncthreads();                                             // 5: attn reads of V done

    {
        const int nd  = tid / 24;
        const int sub = tid - nd * 24;
        const int q   = sub % 12;
        const int hp  = sub / 12;
        float* Ar = sA + (nd * 12 + q) * AST + hp * 32;
#pragma unroll
        for (int hh = 0; hh < 4; hh++) {
#pragma unroll
            for (int e = 0; e < 4; e++) {
                const float2 t = unpack2(o[4 * hh + e]);
                *(float2*)(Ar + 8 * hh + 2 * e) =
                    make_float2(f2tf_f(t.x), f2tf_f(t.y));
            }
        }
    }
    __syncthreads();                                             // 6: attn out staged

    // ---------------- phase D: h = relu(attn @ W24^T + b24) -> sA in place -------
    load_frags(a, sA, row0, gid, tig);
    __syncwarp();
    mma_all(d, a, sW1, gid, tig);
    epi_tf32(d, sA, sBias + 192, row0, gid, tig);
    __syncwarp();

    // ---------------- phase E: out = h @ W25^T + b25 -> global -------------------
    load_frags(a, sA, row0, gid, tig);
    mma_all(d, a, sW0, gid, tig);
    {
        const int rp0 = row0 + gid, rp1 = rp0 + 8;
        const int nA = rp0 / 12, tA = rp0 - nA * 12;
        const int nB = rp1 / 12, tB = rp1 - nB * 12;
        float* o0 = Out + ((size_t)(b * 12 + tA) * Nn + (n0 + nA)) * 64;
        float* o1 = Out + ((size_t)(b * 12 + tB) * Nn + (n0 + nB)) * 64;
        const float* bi = sBias + 256;
#pragma unroll
        for (int nt = 0; nt < 8; nt++) {
            const int c = nt * 8 + tig * 2;
            *(float2*)(o0 + c) = make_float2(d[nt][0] + bi[c], d[nt][1] + bi[c + 1]);
            *(float2*)(o1 + c) = make_float2(d[nt][2] + bi[c], d[nt][3] + bi[c + 1]);
        }
    }
}

extern "C" void kernel_launch(void* const* d_in, const int* in_sizes, int n_in,
                              void* d_out, int out_size)
{
    const float* X     = (const float*)d_in[0];
    const float* STE_P = (const float*)d_in[1];
    const float* STE_Q = (const float*)d_in[2];
    const float* W21   = (const float*)d_in[3];
    const float* b21   = (const float*)d_in[4];
    const float* W22   = (const float*)d_in[5];
    const float* b22   = (const float*)d_in[6];
    const float* W23   = (const float*)d_in[7];
    const float* b23   = (const float*)d_in[8];
    const float* W24   = (const float*)d_in[9];
    const float* b24   = (const float*)d_in[10];
    const float* W25   = (const float*)d_in[11];
    const float* b25   = (const float*)d_in[12];
    float* Out = (float*)d_out;

    const size_t smem_bytes =
        (size_t)(2 * 64 * WST + 320 + 3 * ROWS * AST) * sizeof(float);   // 112,128 B

    cudaFuncSetAttribute(fused_mma_kernel,
                         cudaFuncAttributeMaxDynamicSharedMemorySize,
                         (int)smem_bytes);

    dim3 grid(Nn / NODES, Bsz);   // (625, 8), exact
    fused_mma_kernel<<<grid, THREADS, smem_bytes>>>(
        X, STE_P, STE_Q,
        W21, b21, W22, b22, W23, b23, W24, b24, W25, b25,
        Out);
}

// round 6
// speedup vs baseline: 1.6508x; 1.0118x over previous
#include <cuda_runtime.h>
#include <cstdint>

#define Bsz 8
#define Nn 5000
#define NODES 8            // nodes per block
#define THREADS 192        // 6 warps
#define ROWS 96            // 8 nodes * 12 timesteps
#define NST 802            // node stride (floats) in head-major QKV buffers
#define HST 100            // head stride (floats)

typedef unsigned long long u64;

// ---------------- scalar helpers ----------------
__device__ __forceinline__ uint32_t f2tf(float f) {
    uint32_t r; asm("cvt.rna.tf32.f32 %0, %1;" : "=r"(r) : "f"(f)); return r;
}
__device__ __forceinline__ float f2tf_f(float f) { return __uint_as_float(f2tf(f)); }
__device__ __forceinline__ u64 fma2(u64 a, u64 b, u64 c) {
    u64 d; asm("fma.rn.f32x2 %0, %1, %2, %3;" : "=l"(d) : "l"(a), "l"(b), "l"(c)); return d;
}
__device__ __forceinline__ u64 mul2(u64 a, u64 b) {
    u64 d; asm("mul.rn.f32x2 %0, %1, %2;" : "=l"(d) : "l"(a), "l"(b)); return d;
}
__device__ __forceinline__ u64 dup2(float x) {
    u64 d; unsigned r = __float_as_uint(x);
    asm("mov.b64 %0, {%1, %1};" : "=l"(d) : "r"(r)); return d;
}
__device__ __forceinline__ float2 unpack2(u64 v) {
    unsigned lo, hi;
    asm("mov.b64 {%0, %1}, %2;" : "=r"(lo), "=r"(hi) : "l"(v));
    return make_float2(__uint_as_float(lo), __uint_as_float(hi));
}
__device__ __forceinline__ void mma_tf32(float d[4], const uint32_t a[4],
                                         uint32_t b0, uint32_t b1) {
    asm volatile(
        "mma.sync.aligned.m16n8k8.row.col.f32.tf32.tf32.f32 "
        "{%0,%1,%2,%3}, {%4,%5,%6,%7}, {%8,%9}, {%0,%1,%2,%3};"
        : "+f"(d[0]), "+f"(d[1]), "+f"(d[2]), "+f"(d[3])
        : "r"(a[0]), "r"(a[1]), "r"(a[2]), "r"(a[3]), "r"(b0), "r"(b1));
}
__device__ __forceinline__ void ld_pair(const float* p, uint32_t& lo, uint32_t& hi) {
    const u64 v = *(const u64*)p;
    lo = (uint32_t)v; hi = (uint32_t)(v >> 32);
}

// global row pointer for packed row rp (node = rp/12, t = rp%12)
__device__ __forceinline__ const float* grow(const float* __restrict__ src,
                                             int b, int n0, int rp) {
    const int n = rp / 12;
    const int t = rp - n * 12;
    return src + ((size_t)(b * 12 + t) * Nn + (n0 + n)) * 64;
}

// ---- frag-pair layout + 8-block XOR swizzle --------------------------------
// Logical (row, col) of a 64-wide tf32 matrix is stored at:
//   row*64 + ((blk ^ (row&3))<<3) + pos(j),  blk=col>>3, j=col&7,
//   pos(j) = ((j&3)<<1) | (j>>2)   ->  (tig, tig+4) become adjacent (LDS.64)
// Writers store float4 (cols 4*c4..+3): positions (c4&1) + {0,2,4,6}.
__device__ __forceinline__ void st_frag4(float* __restrict__ dst, int rp, int c4,
                                         float4 v) {
    float* p = dst + rp * 64 + (((c4 >> 1) ^ (rp & 3)) << 3) + (c4 & 1);
    p[0] = f2tf_f(v.x);
    p[2] = f2tf_f(v.y);
    p[4] = f2tf_f(v.z);
    p[6] = f2tf_f(v.w);
}

__device__ __forceinline__ void stage_weight(const float* __restrict__ Wg,
                                             float* __restrict__ sW, int tid)
{
#pragma unroll
    for (int i = 0; i < 6; i++) {
        const int idx = tid + i * THREADS;
        if (idx < 1024) {
            const int n = idx >> 4, c4 = idx & 15;
            st_frag4(sW, n, c4, *(const float4*)(Wg + n * 64 + c4 * 4));
        }
    }
}

// ---------------- warp fragments / mma ----------------
__device__ __forceinline__ void load_frags(uint32_t a[8][4], const float* __restrict__ sA,
                                           int row0, int gid, int tig)
{
    const int r0 = row0 + gid, r1 = r0 + 8;
    const int g3 = gid & 3;
#pragma unroll
    for (int ks = 0; ks < 8; ks++) {
        const int boff = ((ks ^ g3) << 3) + 2 * tig;
        ld_pair(sA + r0 * 64 + boff, a[ks][0], a[ks][2]);
        ld_pair(sA + r1 * 64 + boff, a[ks][1], a[ks][3]);
    }
}

__device__ __forceinline__ void mma_all(float d[8][4], const uint32_t a[8][4],
                                        const float* __restrict__ sW, int gid, int tig)
{
    const int g3 = gid & 3;
#pragma unroll
    for (int nt = 0; nt < 8; nt++) {
        d[nt][0] = 0.f; d[nt][1] = 0.f; d[nt][2] = 0.f; d[nt][3] = 0.f;
        const float* wr = sW + (nt * 8 + gid) * 64;
#pragma unroll
        for (int ks = 0; ks < 8; ks++) {
            uint32_t b0, b1;
            ld_pair(wr + ((ks ^ g3) << 3) + 2 * tig, b0, b1);
            mma_tf32(d[nt], a[ks], b0, b1);
        }
    }
}

// ---------------- epilogues ----------------
// QKV: head-major [node][head][p][8] with bias+relu (f32)
__device__ __forceinline__ void epi_qkv(const float d[8][4], float* __restrict__ dst,
                                        const float* __restrict__ bi,
                                        int row0, int gid, int tig)
{
    const int rp0 = row0 + gid, rp1 = rp0 + 8;
    const int nd0 = rp0 / 12, p0 = rp0 - nd0 * 12;
    const int nd1 = rp1 / 12, p1 = rp1 - nd1 * 12;
    float* d0 = dst + nd0 * NST + p0 * 8 + 2 * tig;
    float* d1 = dst + nd1 * NST + p1 * 8 + 2 * tig;
#pragma unroll
    for (int nt = 0; nt < 8; nt++) {
        const int c = nt * 8 + 2 * tig;
        *(float2*)(d0 + nt * HST) = make_float2(fmaxf(d[nt][0] + bi[c], 0.f),
                                                fmaxf(d[nt][1] + bi[c + 1], 0.f));
        *(float2*)(d1 + nt * HST) = make_float2(fmaxf(d[nt][2] + bi[c], 0.f),
                                                fmaxf(d[nt][3] + bi[c + 1], 0.f));
    }
}

// hidden: back into sA frag layout (bias+relu+tf32)
__device__ __forceinline__ void epi_hidden(const float d[8][4], float* __restrict__ sA,
                                           const float* __restrict__ bi,
                                           int row0, int gid, int tig)
{
    const int rp0 = row0 + gid, rp1 = rp0 + 8;
    const int g3 = gid & 3;
    const int off = (tig & 1) * 4 + (tig >> 1);      // pos(2*tig)
#pragma unroll
    for (int nt = 0; nt < 8; nt++) {
        const int c = nt * 8 + 2 * tig;
        float* p0 = sA + rp0 * 64 + ((nt ^ g3) << 3) + off;
        float* p1 = sA + rp1 * 64 + ((nt ^ g3) << 3) + off;
        p0[0] = f2tf_f(fmaxf(d[nt][0] + bi[c], 0.f));
        p0[2] = f2tf_f(fmaxf(d[nt][1] + bi[c + 1], 0.f));
        p1[0] = f2tf_f(fmaxf(d[nt][2] + bi[c], 0.f));
        p1[2] = f2tf_f(fmaxf(d[nt][3] + bi[c + 1], 0.f));
    }
}

// ---------------- kernel ----------------
__global__ void __launch_bounds__(THREADS, 2)
fused_mma_kernel(const float* __restrict__ X,
                 const float* __restrict__ STE_P,
                 const float* __restrict__ STE_Q,
                 const float* __restrict__ W21, const float* __restrict__ b21,
                 const float* __restrict__ W22, const float* __restrict__ b22,
                 const float* __restrict__ W23, const float* __restrict__ b23,
                 const float* __restrict__ W24, const float* __restrict__ b24,
                 const float* __restrict__ W25, const float* __restrict__ b25,
                 float* __restrict__ Out)
{
    extern __shared__ float sm[];
    float* sW0   = sm;                         // 64*64 frag layout
    float* sW1   = sm + 4096;                  // 64*64
    float* sBias = sm + 8192;                  // 5*64
    float* sA    = sBias + 320;                // 6416 (frag slab / V head-major)
    float* sQ    = sA + 6416;                  // 6416 head-major
    float* sK    = sQ + 6416;                  // 6416 head-major

    const int tid  = threadIdx.x;
    const int w    = tid >> 5;
    const int lane = tid & 31;
    const int gid  = lane >> 2;
    const int tig  = lane & 3;
    const int b    = blockIdx.y;
    const int n0   = blockIdx.x * NODES;
    const int row0 = w * 16;

    if (tid < 64) {
        sBias[tid]       = b21[tid];
        sBias[64 + tid]  = b22[tid];
        sBias[128 + tid] = b23[tid];
        sBias[192 + tid] = b24[tid];
        sBias[256 + tid] = b25[tid];
    }

    // input staging helper indices: each warp covers its 16 rows, 2 rows/iter
    const int srow = (lane >> 4);          // 0/1
    const int sc4  = lane & 15;

    // stage W21 + STE_Q
    stage_weight(W21, sW0, tid);
#pragma unroll
    for (int i = 0; i < 8; i++) {
        const int rp = row0 + i * 2 + srow;
        st_frag4(sA, rp, sc4, *(const float4*)(grow(STE_Q, b, n0, rp) + sc4 * 4));
    }
    __syncthreads();                                           // S1

    uint32_t a[8][4];
    float d[8][4];
    float4 pf[8];

    // ---------------- region A: q = relu(STE_Q @ W21^T + b21) -> sQ -------------
#pragma unroll
    for (int i = 0; i < 8; i++)
        pf[i] = *(const float4*)(grow(STE_P, b, n0, row0 + i * 2 + srow) + sc4 * 4);
    load_frags(a, sA, row0, gid, tig);
    __syncwarp();
#pragma unroll
    for (int i = 0; i < 8; i++)
        st_frag4(sA, row0 + i * 2 + srow, sc4, pf[i]);
    stage_weight(W22, sW1, tid);
    mma_all(d, a, sW0, gid, tig);
    epi_qkv(d, sQ, sBias, row0, gid, tig);
    __syncthreads();                                           // S2

    // ---------------- region B: k = relu(STE_P @ W22^T + b22) -> sK -------------
#pragma unroll
    for (int i = 0; i < 8; i++)
        pf[i] = *(const float4*)(grow(X, b, n0, row0 + i * 2 + srow) + sc4 * 4);
    load_frags(a, sA, row0, gid, tig);
    __syncwarp();
#pragma unroll
    for (int i = 0; i < 8; i++)
        st_frag4(sA, row0 + i * 2 + srow, sc4, pf[i]);
    stage_weight(W23, sW0, tid);
    mma_all(d, a, sW1, gid, tig);
    epi_qkv(d, sK, sBias + 64, row0, gid, tig);
    __syncwarp();
    load_frags(a, sA, row0, gid, tig);       // pre-load phase-C frags (X)
    __syncthreads();                                           // S3

    // ---------------- region C: v = relu(X @ W23^T + b23) -> sA (head-major) ----
    stage_weight(W24, sW1, tid);
    mma_all(d, a, sW0, gid, tig);
    epi_qkv(d, sA, sBias + 128, row0, gid, tig);               // V overwrites X slab
    __syncthreads();                                           // S4: Q,K,V ready

    // ---------------- attention: thread = (node, head, q-quarter) ---------------
    // h = lane&7 ; pairidx = w*4 + (lane>>3) -> nd = pi/3, q0 = (pi%3)*4
    u64 o[4][4];
    {
        const int h  = lane & 7;
        const int pi = w * 4 + (lane >> 3);
        const int nd = pi / 3;
        const int q0 = (pi - nd * 3) * 4;
        const float* Qb = sQ + nd * NST + h * HST + q0 * 8;
        const float* Kb = sK + nd * NST + h * HST;
        const float* Vb = sA + nd * NST + h * HST;
        const float scale = 0.35355339059327373f;              // 1/sqrt(8)

        u64 Qp[4][4];
#pragma unroll
        for (int jq = 0; jq < 4; jq++)
#pragma unroll
            for (int e = 0; e < 4; e++)
                Qp[jq][e] = *(const u64*)(Qb + jq * 8 + 2 * e);

        float s[4][12];
        float mx0 = -1e30f, mx1 = -1e30f, mx2 = -1e30f, mx3 = -1e30f;
#pragma unroll
        for (int p = 0; p < 12; p++) {
            const float* kr = Kb + p * 8;
            const u64 k0 = *(const u64*)(kr + 0);
            const u64 k1 = *(const u64*)(kr + 2);
            const u64 k2 = *(const u64*)(kr + 4);
            const u64 k3 = *(const u64*)(kr + 6);
#pragma unroll
            for (int jq = 0; jq < 4; jq++) {
                u64 dd = fma2(Qp[jq][0], k0, fma2(Qp[jq][1], k1,
                         fma2(Qp[jq][2], k2, mul2(Qp[jq][3], k3))));
                const float2 t = unpack2(dd);
                s[jq][p] = (t.x + t.y) * scale;
            }
            mx0 = fmaxf(mx0, s[0][p]); mx1 = fmaxf(mx1, s[1][p]);
            mx2 = fmaxf(mx2, s[2][p]); mx3 = fmaxf(mx3, s[3][p]);
        }
        float inv[4];
        {
            float sum0 = 0.f, sum1 = 0.f, sum2 = 0.f, sum3 = 0.f;
#pragma unroll
            for (int p = 0; p < 12; p++) {
                s[0][p] = __expf(s[0][p] - mx0); sum0 += s[0][p];
                s[1][p] = __expf(s[1][p] - mx1); sum1 += s[1][p];
                s[2][p] = __expf(s[2][p] - mx2); sum2 += s[2][p];
                s[3][p] = __expf(s[3][p] - mx3); sum3 += s[3][p];
            }
            inv[0] = __fdividef(1.f, sum0); inv[1] = __fdividef(1.f, sum1);
            inv[2] = __fdividef(1.f, sum2); inv[3] = __fdividef(1.f, sum3);
        }
        const u64 z = dup2(0.f);
#pragma unroll
        for (int jq = 0; jq < 4; jq++)
#pragma unroll
            for (int e = 0; e < 4; e++) o[jq][e] = z;
#pragma unroll
        for (int p = 0; p < 12; p++) {
            const float* vr = Vb + p * 8;
            const u64 v0 = *(const u64*)(vr + 0);
            const u64 v1 = *(const u64*)(vr + 2);
            const u64 v2 = *(const u64*)(vr + 4);
            const u64 v3 = *(const u64*)(vr + 6);
#pragma unroll
            for (int jq = 0; jq < 4; jq++) {
                const u64 aw = dup2(s[jq][p] * inv[jq]);
                o[jq][0] = fma2(v0, aw, o[jq][0]);
                o[jq][1] = fma2(v1, aw, o[jq][1]);
                o[jq][2] = fma2(v2, aw, o[jq][2]);
                o[jq][3] = fma2(v3, aw, o[jq][3]);
            }
        }
    }
    stage_weight(W25, sW0, tid);
    __syncthreads();                                           // S5: V reads done

    // write attn-out into sA frag layout (tf32)
    {
        const int h  = lane & 7;
        const int pi = w * 4 + (lane >> 3);
        const int nd = pi / 3;
        const int q0 = (pi - nd * 3) * 4;
#pragma unroll
        for (int jq = 0; jq < 4; jq++) {
            const int row = nd * 12 + q0 + jq;
            float* base = sA + row * 64 + ((h ^ (row & 3)) << 3);
#pragma unroll
            for (int e = 0; e < 4; e++) {
                const int off = (e & 1) * 4 + (e >> 1);        // pos(2e)
                const float2 t = unpack2(o[jq][e]);
                base[off]     = f2tf_f(t.x);
                base[off + 2] = f2tf_f(t.y);
            }
        }
    }
    __syncthreads();                                           // S6: attn-out visible

    // ---------------- phase D: h = relu(attn @ W24^T + b24) -> sA ---------------
    load_frags(a, sA, row0, gid, tig);
    __syncwarp();
    mma_all(d, a, sW1, gid, tig);
    epi_hidden(d, sA, sBias + 192, row0, gid, tig);
    __syncwarp();

    // ---------------- phase E: out = h @ W25^T + b25 -> global ------------------
    load_frags(a, sA, row0, gid, tig);
    mma_all(d, a, sW0, gid, tig);
    {
        const int rp0 = row0 + gid, rp1 = rp0 + 8;
        const int nA = rp0 / 12, tA = rp0 - nA * 12;
        const int nB = rp1 / 12, tB = rp1 - nB * 12;
        float* o0 = Out + ((size_t)(b * 12 + tA) * Nn + (n0 + nA)) * 64;
        float* o1 = Out + ((size_t)(b * 12 + tB) * Nn + (n0 + nB)) * 64;
        const float* bi = sBias + 256;
#pragma unroll
        for (int nt = 0; nt < 8; nt++) {
            const int c = nt * 8 + tig * 2;
            *(float2*)(o0 + c) = make_float2(d[nt][0] + bi[c], d[nt][1] + bi[c + 1]);
            *(float2*)(o1 + c) = make_float2(d[nt][2] + bi[c], d[nt][3] + bi[c + 1]);
        }
    }
}

extern "C" void kernel_launch(void* const* d_in, const int* in_sizes, int n_in,
                              void* d_out, int out_size)
{
    const float* X     = (const float*)d_in[0];
    const float* STE_P = (const float*)d_in[1];
    const float* STE_Q = (const float*)d_in[2];
    const float* W21   = (const float*)d_in[3];
    const float* b21   = (const float*)d_in[4];
    const float* W22   = (const float*)d_in[5];
    const float* b22   = (const float*)d_in[6];
    const float* W23   = (const float*)d_in[7];
    const float* b23   = (const float*)d_in[8];
    const float* W24   = (const float*)d_in[9];
    const float* b24   = (const float*)d_in[10];
    const float* W25   = (const float*)d_in[11];
    const float* b25   = (const float*)d_in[12];
    float* Out = (float*)d_out;

    const size_t smem_bytes =
        (size_t)(2 * 4096 + 320 + 3 * 6416) * sizeof(float);   // 111,040 B

    cudaFuncSetAttribute(fused_mma_kernel,
                         cudaFuncAttributeMaxDynamicSharedMemorySize,
                         (int)smem_bytes);

    dim3 grid(Nn / NODES, Bsz);   // (625, 8)
    fused_mma_kernel<<<grid, THREADS, smem_bytes>>>(
        X, STE_P, STE_Q,
        W21, b21, W22, b22, W23, b23, W24, b24, W25, b25,
        Out);
}

// round 7
// speedup vs baseline: 2.5362x; 1.5364x over previous
#include <cuda_runtime.h>
#include <cstdint>

#define Bsz 8
#define Nn 5000
#define NODES 8
#define THREADS 192          // 6 warps
#define ROWS 96
// Q/K fp16 head-major strides (uint = f16x2 units)
#define NSTU 420
#define HSTU 52
// V f32 head-major strides (float units)
#define NSTF 802
#define HSTF 100

// smem layout in 4B units
#define U_W    0            // 64*32 = 2048
#define U_BIAS 2048         // 320 f32
#define U_A    2368         // 96*32 = 3072
#define U_Q    5440         // 8*420 = 3360
#define U_K    8800         // 3360
#define U_V    12160        // 6416 f32
#define U_TOT  18576        // 74304 bytes

typedef unsigned long long u64;

// ---------------- helpers ----------------
__device__ __forceinline__ u64 fma2(u64 a, u64 b, u64 c) {
    u64 d; asm("fma.rn.f32x2 %0, %1, %2, %3;" : "=l"(d) : "l"(a), "l"(b), "l"(c)); return d;
}
__device__ __forceinline__ u64 mul2(u64 a, u64 b) {
    u64 d; asm("mul.rn.f32x2 %0, %1, %2;" : "=l"(d) : "l"(a), "l"(b)); return d;
}
__device__ __forceinline__ u64 dup2(float x) {
    u64 d; unsigned r = __float_as_uint(x);
    asm("mov.b64 %0, {%1, %1};" : "=l"(d) : "r"(r)); return d;
}
__device__ __forceinline__ float2 unpack2(u64 v) {
    unsigned lo, hi;
    asm("mov.b64 {%0, %1}, %2;" : "=r"(lo), "=r"(hi) : "l"(v));
    return make_float2(__uint_as_float(lo), __uint_as_float(hi));
}
// pack two f32 -> f16x2 (lo = x, hi = y)
__device__ __forceinline__ unsigned ph2(float x, float y) {
    unsigned r;
    asm("cvt.rn.f16x2.f32 %0, %1, %2;" : "=r"(r) : "f"(y), "f"(x));
    return r;
}
// f16x2 -> f32x2 (u64)
__device__ __forceinline__ u64 h2f2(unsigned h) {
    u64 r;
    asm("{ .reg .b16 l, h; .reg .f32 f0, f1;\n\t"
        "mov.b32 {l, h}, %1;\n\t"
        "cvt.f32.f16 f0, l;\n\tcvt.f32.f16 f1, h;\n\t"
        "mov.b64 %0, {f0, f1}; }" : "=l"(r) : "r"(h));
    return r;
}
__device__ __forceinline__ float h2_lo(unsigned h) {
    float f;
    asm("{ .reg .b16 l, hh; mov.b32 {l, hh}, %1; cvt.f32.f16 %0, l; }" : "=f"(f) : "r"(h));
    return f;
}
__device__ __forceinline__ float h2_hi(unsigned h) {
    float f;
    asm("{ .reg .b16 l, hh; mov.b32 {l, hh}, %1; cvt.f32.f16 %0, hh; }" : "=f"(f) : "r"(h));
    return f;
}
__device__ __forceinline__ void mma_f16(float d[4], const unsigned a[4],
                                        unsigned b0, unsigned b1) {
    asm volatile(
        "mma.sync.aligned.m16n8k16.row.col.f32.f16.f16.f32 "
        "{%0,%1,%2,%3}, {%4,%5,%6,%7}, {%8,%9}, {%0,%1,%2,%3};"
        : "+f"(d[0]), "+f"(d[1]), "+f"(d[2]), "+f"(d[3])
        : "r"(a[0]), "r"(a[1]), "r"(a[2]), "r"(a[3]), "r"(b0), "r"(b1));
}
__device__ __forceinline__ void ld_pair(const unsigned* p, unsigned& lo, unsigned& hi) {
    const u64 v = *(const u64*)p;
    lo = (unsigned)v; hi = (unsigned)(v >> 32);
}
// pos(jj) for frag-pair layout: (tig, tig+4) adjacent
__device__ __forceinline__ int posj(int jj) { return ((jj & 3) << 1) | (jj >> 2); }

// ---------------- kernel ----------------
__global__ void __launch_bounds__(THREADS, 3)
fused_h16_kernel(const float* __restrict__ X,
                 const float* __restrict__ STE_P,
                 const float* __restrict__ STE_Q,
                 const float* __restrict__ W21, const float* __restrict__ b21,
                 const float* __restrict__ W22, const float* __restrict__ b22,
                 const float* __restrict__ W23, const float* __restrict__ b23,
                 const float* __restrict__ W24, const float* __restrict__ b24,
                 const float* __restrict__ W25, const float* __restrict__ b25,
                 float* __restrict__ Out)
{
    extern __shared__ unsigned sm[];
    unsigned* sW = sm + U_W;
    float*    sBias = (float*)(sm + U_BIAS);
    unsigned* sA = sm + U_A;
    unsigned* sQ = sm + U_Q;
    unsigned* sK = sm + U_K;
    float*    sV = (float*)(sm + U_V);

    const int tid  = threadIdx.x;
    const int w    = tid >> 5;
    const int lane = tid & 31;
    const int gid  = lane >> 2;
    const int tig  = lane & 3;
    const int g3   = gid & 3;
    const int b    = blockIdx.y;
    const int n0   = blockIdx.x * NODES;
    const int row0 = w * 16;

    // epilogue row mapping (constant per thread)
    const int rp0 = row0 + gid, rp1 = rp0 + 8;
    const int nd0 = rp0 / 12, p0 = rp0 - nd0 * 12;
    const int nd1 = rp1 / 12, p1 = rp1 - nd1 * 12;

    // staging indices
    const int srow = lane >> 4;          // 0/1
    const int sc4  = lane & 15;
    const int jj0  = (2 * sc4) & 7;
    const int sp0  = posj(jj0);
    int goff[8]; int sapos[8];
#pragma unroll
    for (int i = 0; i < 8; i++) {
        const int rp = row0 + 2 * i + srow;
        const int n = rp / 12, t = rp - n * 12;
        goff[i]  = ((b * 12 + t) * Nn + n0 + n) * 64 + sc4 * 4;
        sapos[i] = rp * 32 + (((sc4 >> 2) ^ (rp & 3)) << 3) + sp0;
    }

    if (tid < 64) {
        sBias[tid]       = b21[tid];
        sBias[64 + tid]  = b22[tid];
        sBias[128 + tid] = b23[tid];
        sBias[192 + tid] = b24[tid];
        sBias[256 + tid] = b25[tid];
    }

#define STAGE_W(Wg)                                                         \
    {                                                                       \
        _Pragma("unroll")                                                   \
        for (int it = 0; it < 6; it++) {                                    \
            const int idx = tid + it * THREADS;                             \
            if (idx < 1024) {                                               \
                const int n = idx >> 4, c4 = idx & 15;                      \
                const float4 v = *(const float4*)((Wg) + n * 64 + c4 * 4);  \
                const int jw = (2 * c4) & 7;                                \
                const int a0 = n * 32 + (((c4 >> 2) ^ (n & 3)) << 3) + posj(jw); \
                sW[a0]     = ph2(v.x, v.y);                                 \
                sW[a0 + 2] = ph2(v.z, v.w);                                 \
            }                                                               \
        }                                                                   \
    }

#define STAGE_IN(src)                                                       \
    {                                                                       \
        _Pragma("unroll")                                                   \
        for (int i = 0; i < 8; i++) {                                       \
            const float4 v = *(const float4*)((src) + goff[i]);             \
            sA[sapos[i]]     = ph2(v.x, v.y);                               \
            sA[sapos[i] + 2] = ph2(v.z, v.w);                               \
        }                                                                   \
    }

#define LOAD_FRAGS(a)                                                       \
    {                                                                       \
        _Pragma("unroll")                                                   \
        for (int kc = 0; kc < 4; kc++) {                                    \
            const int off = ((kc ^ g3) << 3) + 2 * tig;                     \
            ld_pair(sA + rp0 * 32 + off, (a)[kc][0], (a)[kc][2]);           \
            ld_pair(sA + rp1 * 32 + off, (a)[kc][1], (a)[kc][3]);           \
        }                                                                   \
    }

#define MMA_ALL(d, a)                                                       \
    {                                                                       \
        _Pragma("unroll")                                                   \
        for (int nt = 0; nt < 8; nt++) {                                    \
            (d)[nt][0] = 0.f; (d)[nt][1] = 0.f; (d)[nt][2] = 0.f; (d)[nt][3] = 0.f; \
            const unsigned* wr = sW + (nt * 8 + gid) * 32;                  \
            _Pragma("unroll")                                               \
            for (int kc = 0; kc < 4; kc++) {                                \
                unsigned b0, b1;                                            \
                ld_pair(wr + ((kc ^ g3) << 3) + 2 * tig, b0, b1);           \
                mma_f16((d)[nt], (a)[kc], b0, b1);                          \
            }                                                               \
        }                                                                   \
    }

// Q/K epilogue: fp16 head-major
#define EPI_QK(dst, boff)                                                   \
    {                                                                       \
        const float* bi = sBias + (boff);                                   \
        _Pragma("unroll")                                                   \
        for (int nt = 0; nt < 8; nt++) {                                    \
            const int c = nt * 8 + 2 * tig;                                 \
            (dst)[nd0 * NSTU + nt * HSTU + p0 * 4 + tig] =                  \
                ph2(fmaxf(d[nt][0] + bi[c], 0.f), fmaxf(d[nt][1] + bi[c + 1], 0.f)); \
            (dst)[nd1 * NSTU + nt * HSTU + p1 * 4 + tig] =                  \
                ph2(fmaxf(d[nt][2] + bi[c], 0.f), fmaxf(d[nt][3] + bi[c + 1], 0.f)); \
        }                                                                   \
    }

    unsigned a[4][4];
    float d[8][4];

    // ---- setup: W21 + STE_Q staged ----
    STAGE_W(W21);
    STAGE_IN(STE_Q);
    __syncthreads();                                        // S1

    // ---- phase A: q -> sQ (fp16) ----
    LOAD_FRAGS(a);
    MMA_ALL(d, a);
    EPI_QK(sQ, 0);
    __syncthreads();                                        // S2
    STAGE_W(W22);
    STAGE_IN(STE_P);
    __syncthreads();                                        // S3

    // ---- phase B: k -> sK (fp16) ----
    LOAD_FRAGS(a);
    MMA_ALL(d, a);
    EPI_QK(sK, 64);
    __syncthreads();                                        // S4
    STAGE_W(W23);
    STAGE_IN(X);
    __syncthreads();                                        // S5

    // ---- phase C: v -> sV (f32 head-major) ----
    LOAD_FRAGS(a);
    MMA_ALL(d, a);
    {
        const float* bi = sBias + 128;
#pragma unroll
        for (int nt = 0; nt < 8; nt++) {
            const int c = nt * 8 + 2 * tig;
            *(float2*)(sV + nd0 * NSTF + nt * HSTF + p0 * 8 + 2 * tig) =
                make_float2(fmaxf(d[nt][0] + bi[c], 0.f), fmaxf(d[nt][1] + bi[c + 1], 0.f));
            *(float2*)(sV + nd1 * NSTF + nt * HSTF + p1 * 8 + 2 * tig) =
                make_float2(fmaxf(d[nt][2] + bi[c], 0.f), fmaxf(d[nt][3] + bi[c + 1], 0.f));
        }
    }
    __syncthreads();                                        // S6

    // ---- attention (f32 math; Q/K cvt from fp16; V f32) + stage W24 ----
    STAGE_W(W24);
    {
        const int h  = lane & 7;
        const int pi = w * 4 + (lane >> 3);
        const int nd = pi / 3;
        const int q0 = (pi - nd * 3) * 4;
        const unsigned* Qb = sQ + nd * NSTU + h * HSTU + q0 * 4;
        const unsigned* Kb = sK + nd * NSTU + h * HSTU;
        const float*    Vb = sV + nd * NSTF + h * HSTF;
        const float scale = 0.35355339059327373f;

        u64 Qp[4][4];
#pragma unroll
        for (int jq = 0; jq < 4; jq++) {
            const uint4 qv = *(const uint4*)(Qb + jq * 4);
            Qp[jq][0] = h2f2(qv.x); Qp[jq][1] = h2f2(qv.y);
            Qp[jq][2] = h2f2(qv.z); Qp[jq][3] = h2f2(qv.w);
        }
        unsigned e2[4][6];
        float elo[4];
        float sum0 = 0.f, sum1 = 0.f, sum2 = 0.f, sum3 = 0.f;
#pragma unroll
        for (int p = 0; p < 12; p++) {
            const uint4 kv = *(const uint4*)(Kb + p * 4);
            const u64 k0 = h2f2(kv.x), k1 = h2f2(kv.y);
            const u64 k2 = h2f2(kv.z), k3 = h2f2(kv.w);
            float ee[4];
#pragma unroll
            for (int jq = 0; jq < 4; jq++) {
                u64 dd = fma2(Qp[jq][0], k0, fma2(Qp[jq][1], k1,
                         fma2(Qp[jq][2], k2, mul2(Qp[jq][3], k3))));
                const float2 t = unpack2(dd);
                ee[jq] = __expf(fmaf(t.x + t.y, scale, -8.0f));   // max-free softmax
            }
            sum0 += ee[0]; sum1 += ee[1]; sum2 += ee[2]; sum3 += ee[3];
            if (p & 1) {
#pragma unroll
                for (int jq = 0; jq < 4; jq++) e2[jq][p >> 1] = ph2(elo[jq], ee[jq]);
            } else {
#pragma unroll
                for (int jq = 0; jq < 4; jq++) elo[jq] = ee[jq];
            }
        }
        const float inv0 = __fdividef(1.f, sum0);
        const float inv1 = __fdividef(1.f, sum1);
        const float inv2 = __fdividef(1.f, sum2);
        const float inv3 = __fdividef(1.f, sum3);
        const float inv[4] = { inv0, inv1, inv2, inv3 };

        u64 o[4][4];
        const u64 z = dup2(0.f);
#pragma unroll
        for (int jq = 0; jq < 4; jq++)
#pragma unroll
            for (int e = 0; e < 4; e++) o[jq][e] = z;
#pragma unroll
        for (int p = 0; p < 12; p++) {
            const float* vr = Vb + p * 8;
            const u64 v0 = *(const u64*)(vr + 0);
            const u64 v1 = *(const u64*)(vr + 2);
            const u64 v2 = *(const u64*)(vr + 4);
            const u64 v3 = *(const u64*)(vr + 6);
#pragma unroll
            for (int jq = 0; jq < 4; jq++) {
                const float ev = (p & 1) ? h2_hi(e2[jq][p >> 1]) : h2_lo(e2[jq][p >> 1]);
                const u64 aw = dup2(ev * inv[jq]);
                o[jq][0] = fma2(v0, aw, o[jq][0]);
                o[jq][1] = fma2(v1, aw, o[jq][1]);
                o[jq][2] = fma2(v2, aw, o[jq][2]);
                o[jq][3] = fma2(v3, aw, o[jq][3]);
            }
        }
        // write attn-out into sA fp16 frag layout (rows are warp-local)
#pragma unroll
        for (int jq = 0; jq < 4; jq++) {
            const int row = nd * 12 + q0 + jq;
            unsigned* base = sA + row * 32 + (((h >> 1) ^ (row & 3)) << 3);
#pragma unroll
            for (int e = 0; e < 4; e++) {
                const int jj = ((h & 1) << 2) + e;
                const float2 t = unpack2(o[jq][e]);
                base[posj(jj)] = ph2(t.x, t.y);
            }
        }
    }
    __syncthreads();                                        // S7 (W24 + attn staging order)

    // ---- phase D: h = relu(attn @ W24^T + b24) -> sA in place (warp-local) ----
    LOAD_FRAGS(a);
    __syncwarp();
    MMA_ALL(d, a);
    {
        const float* bi = sBias + 192;
#pragma unroll
        for (int nt = 0; nt < 8; nt++) {
            const int c = nt * 8 + 2 * tig;
            const int colu = 4 * nt + tig;
            const int blk = colu >> 3, jj = colu & 7;
            sA[rp0 * 32 + ((blk ^ (rp0 & 3)) << 3) + posj(jj)] =
                ph2(fmaxf(d[nt][0] + bi[c], 0.f), fmaxf(d[nt][1] + bi[c + 1], 0.f));
            sA[rp1 * 32 + ((blk ^ (rp1 & 3)) << 3) + posj(jj)] =
                ph2(fmaxf(d[nt][2] + bi[c], 0.f), fmaxf(d[nt][3] + bi[c + 1], 0.f));
        }
    }
    __syncthreads();                                        // S8 (sW free)
    STAGE_W(W25);
    __syncthreads();                                        // S9

    // ---- phase E: out = h @ W25^T + b25 -> global ----
    LOAD_FRAGS(a);
    MMA_ALL(d, a);
    {
        float* o0 = Out + ((size_t)(b * 12 + p0) * Nn + (n0 + nd0)) * 64;
        float* o1 = Out + ((size_t)(b * 12 + p1) * Nn + (n0 + nd1)) * 64;
        const float* bi = sBias + 256;
#pragma unroll
        for (int nt = 0; nt < 8; nt++) {
            const int c = nt * 8 + tig * 2;
            *(float2*)(o0 + c) = make_float2(d[nt][0] + bi[c], d[nt][1] + bi[c + 1]);
            *(float2*)(o1 + c) = make_float2(d[nt][2] + bi[c], d[nt][3] + bi[c + 1]);
        }
    }
#undef STAGE_W
#undef STAGE_IN
#undef LOAD_FRAGS
#undef MMA_ALL
#undef EPI_QK
}

extern "C" void kernel_launch(void* const* d_in, const int* in_sizes, int n_in,
                              void* d_out, int out_size)
{
    const float* X     = (const float*)d_in[0];
    const float* STE_P = (const float*)d_in[1];
    const float* STE_Q = (const float*)d_in[2];
    const float* W21   = (const float*)d_in[3];
    const float* b21   = (const float*)d_in[4];
    const float* W22   = (const float*)d_in[5];
    const float* b22   = (const float*)d_in[6];
    const float* W23   = (const float*)d_in[7];
    const float* b23   = (const float*)d_in[8];
    const float* W24   = (const float*)d_in[9];
    const float* b24   = (const float*)d_in[10];
    const float* W25   = (const float*)d_in[11];
    const float* b25   = (const float*)d_in[12];
    float* Out = (float*)d_out;

    const size_t smem_bytes = (size_t)U_TOT * 4;            // 74,304 B -> 3 CTAs/SM

    cudaFuncSetAttribute(fused_h16_kernel,
                         cudaFuncAttributeMaxDynamicSharedMemorySize,
                         (int)smem_bytes);

    dim3 grid(Nn / NODES, Bsz);   // (625, 8)
    fused_h16_kernel<<<grid, THREADS, smem_bytes>>>(
        X, STE_P, STE_Q,
        W21, b21, W22, b22, W23, b23, W24, b24, W25, b25,
        Out);
}